// round 15
// baseline (speedup 1.0000x reference)
#include <cuda_runtime.h>
#include <cuda_bf16.h>
#include <cstdint>

#define BATCH 8
#define NPIX  4096
#define CQK   128
#define CV    256
#define BJ    32

__device__ __nv_bfloat16 g_Qhi[BATCH * NPIX * CQK];
__device__ __nv_bfloat16 g_Qlo[BATCH * NPIX * CQK];
__device__ __nv_bfloat16 g_Khi[BATCH * NPIX * CQK];
__device__ __nv_bfloat16 g_Klo[BATCH * NPIX * CQK];
__device__ __nv_bfloat16 g_Vthi[BATCH * CV * NPIX];  // [b][c][n] transposed
__device__ __nv_bfloat16 g_Vtlo[BATCH * CV * NPIX];

__device__ __forceinline__ uint32_t smem_u32(const void* p) {
    uint32_t a;
    asm("{ .reg .u64 t; cvta.to.shared.u64 t, %1; cvt.u32.u64 %0, t; }" : "=r"(a) : "l"(p));
    return a;
}
__device__ __forceinline__ void ldsm4(uint32_t r[4], uint32_t addr) {
    asm volatile("ldmatrix.sync.aligned.m8n8.x4.shared.b16 {%0,%1,%2,%3}, [%4];"
                 : "=r"(r[0]), "=r"(r[1]), "=r"(r[2]), "=r"(r[3]) : "r"(addr));
}
__device__ __forceinline__ void mma_bf16(float d[4], const uint32_t a[4],
                                         uint32_t b0, uint32_t b1) {
    asm("mma.sync.aligned.m16n8k16.row.col.f32.bf16.bf16.f32 "
        "{%0,%1,%2,%3}, {%4,%5,%6,%7}, {%8,%9}, {%0,%1,%2,%3};"
        : "+f"(d[0]), "+f"(d[1]), "+f"(d[2]), "+f"(d[3])
        : "r"(a[0]), "r"(a[1]), "r"(a[2]), "r"(a[3]), "r"(b0), "r"(b1));
}

__device__ __forceinline__ float exp2_fast(float x) {
    x = fmaxf(x, -126.0f);
    float fl = floorf(x), f = x - fl;
    float p = 1.87757667e-3f;
    p = fmaf(p, f, 8.98934058e-3f); p = fmaf(p, f, 5.58263180e-2f);
    p = fmaf(p, f, 2.40153617e-1f); p = fmaf(p, f, 6.93153073e-1f);
    p = fmaf(p, f, 9.99999994e-1f);
    return p * __int_as_float(((int)fl + 127) << 23);
}

// ============================================================================
// Projection -> bf16 hi/lo split. TR=false: [b][i][o]; TR=true: [b][o][i].
// ============================================================================
template<int CIN, int COUT, bool TR>
__global__ __launch_bounds__(256) void proj_split(
    const float* __restrict__ in, const float* __restrict__ W,
    const float* __restrict__ bias, __nv_bfloat16* __restrict__ ohi,
    __nv_bfloat16* __restrict__ olo, float scale)
{
    __shared__ float sIn[32][64], sWT[32][64], sOut[64][68];
    const int b = blockIdx.z, i0 = blockIdx.x * 64, o0 = blockIdx.y * 64;
    const int tx = threadIdx.x, ti = tx & 15, to = tx >> 4;
    const float* inb = in + (size_t)b * CIN * NPIX + i0;

    float acc[4][4];
#pragma unroll
    for (int a = 0; a < 4; a++)
#pragma unroll
        for (int c = 0; c < 4; c++) acc[a][c] = 0.0f;

    for (int k0 = 0; k0 < CIN; k0 += 32) {
        for (int t = tx; t < 512; t += 256) {
            int k = t >> 4, i4 = (t & 15) << 2;
            *(float4*)&sIn[k][i4] = *(const float4*)&inb[(size_t)(k0 + k) * NPIX + i4];
        }
        for (int t = tx; t < 512; t += 256) {
            int o = t >> 3, k4 = (t & 7) << 2;
            float4 w = *(const float4*)&W[(size_t)(o0 + o) * CIN + k0 + k4];
            sWT[k4][o] = w.x; sWT[k4 + 1][o] = w.y; sWT[k4 + 2][o] = w.z; sWT[k4 + 3][o] = w.w;
        }
        __syncthreads();
#pragma unroll
        for (int k = 0; k < 32; k++) {
            float4 a = *(float4*)&sIn[k][ti * 4];
            float4 w = *(float4*)&sWT[k][to * 4];
            float av[4] = {a.x, a.y, a.z, a.w}, wv[4] = {w.x, w.y, w.z, w.w};
#pragma unroll
            for (int ii = 0; ii < 4; ii++)
#pragma unroll
                for (int oo = 0; oo < 4; oo++)
                    acc[ii][oo] = fmaf(av[ii], wv[oo], acc[ii][oo]);
        }
        __syncthreads();
    }
#pragma unroll
    for (int ii = 0; ii < 4; ii++)
#pragma unroll
        for (int oo = 0; oo < 4; oo++)
            sOut[ti * 4 + ii][to * 4 + oo] = acc[ii][oo];
    __syncthreads();

    for (int t = tx; t < 1024; t += 256) {
        float x[4];
        size_t g;
        if (!TR) {
            int i = t >> 4, o4 = (t & 15) << 2;
            float4 v = *(float4*)&sOut[i][o4];
            float4 bb = *(const float4*)&bias[o0 + o4];
            x[0] = (v.x + bb.x) * scale; x[1] = (v.y + bb.y) * scale;
            x[2] = (v.z + bb.z) * scale; x[3] = (v.w + bb.w) * scale;
            g = ((size_t)b * NPIX + i0 + i) * COUT + o0 + o4;
        } else {
            int o = t >> 4, i4 = (t & 15) << 2;
            float bb = bias[o0 + o];
#pragma unroll
            for (int e = 0; e < 4; e++) x[e] = (sOut[i4 + e][o] + bb) * scale;
            g = ((size_t)b * COUT + o0 + o) * NPIX + i0 + i4;
        }
#pragma unroll
        for (int e = 0; e < 4; e++) {
            __nv_bfloat16 h = __float2bfloat16_rn(x[e]);
            ohi[g + e] = h;
            olo[g + e] = __float2bfloat16_rn(x[e] - __bfloat162float(h));
        }
    }
}

// ============================================================================
// HMMA flash attention + fuse — 128 threads / 4 warps, 64 i-rows per CTA,
// BJ=32, 91 KB smem -> 2 CTAs/SM for tensor-pipe overlap.
// Q/K rows: 256B data, stride 272B ((17r+c)%8 conflict-free for ldmatrix).
// Vt rows: 64B data, stride 80B ((5r+c)%8 conflict-free).
// ============================================================================
#define RQK 272
#define RV  80
#define SQH 0
#define SQL 17408
#define SKH 34816
#define SKL 43520
#define SVH 52224
#define SVL 72704
#define SMTOT 93184

__global__ __launch_bounds__(128, 2) void flash_hmma(
    const __nv_bfloat16* __restrict__ Qhi, const __nv_bfloat16* __restrict__ Qlo,
    const __nv_bfloat16* __restrict__ Khi, const __nv_bfloat16* __restrict__ Klo,
    const __nv_bfloat16* __restrict__ Vhi, const __nv_bfloat16* __restrict__ Vlo,
    const float* __restrict__ motion, float* __restrict__ out)
{
    extern __shared__ char smem[];
    const uint32_t sb = smem_u32(smem);
    const int tx = threadIdx.x, wid = tx >> 5, lane = tx & 31;
    const int b = blockIdx.y, i0 = blockIdx.x * 64;
    const int g = lane >> 2, t = lane & 3;
    const int mr = lane >> 3, rr = lane & 7;   // ldmatrix role: matrix idx, row

    // per-lane ldmatrix base addresses
    const uint32_t aQ = sb + SQH + (uint32_t)(wid * 16 + rr + (mr & 1) * 8) * RQK + (mr >> 1) * 16;
    const uint32_t aK = sb + SKH + (uint32_t)(rr + (mr >> 1) * 8) * RQK + (mr & 1) * 16;
    const uint32_t aV = sb + SVH + (uint32_t)(rr + (mr >> 1) * 8) * RV + (mr & 1) * 16;

    // fill Q (64 rows x 16 chunks of 16B), hi+lo
    {
        const size_t qb = ((size_t)b * NPIX + i0) * CQK;
        for (int it = tx; it < 1024; it += 128) {
            int row = it >> 4, ch = it & 15;
            uint32_t d = (uint32_t)row * RQK + ch * 16;
            size_t s = qb + (size_t)row * CQK + ch * 8;
            *(uint4*)(smem + SQH + d) = *(const uint4*)(Qhi + s);
            *(uint4*)(smem + SQL + d) = *(const uint4*)(Qlo + s);
        }
    }

    float D[32][4];
#pragma unroll
    for (int nb = 0; nb < 32; nb++)
#pragma unroll
        for (int e = 0; e < 4; e++) D[nb][e] = 0.0f;
    float L0 = 0.0f, L1 = 0.0f;

    for (int jt = 0; jt < NPIX / BJ; jt++) {
        __syncthreads();   // prev tile's K/V reads done before refill
        {
            const size_t kb = ((size_t)b * NPIX + jt * BJ) * CQK;
            for (int it = tx; it < 512; it += 128) {
                int row = it >> 4, ch = it & 15;
                uint32_t d = (uint32_t)row * RQK + ch * 16;
                size_t s = kb + (size_t)row * CQK + ch * 8;
                *(uint4*)(smem + SKH + d) = *(const uint4*)(Khi + s);
                *(uint4*)(smem + SKL + d) = *(const uint4*)(Klo + s);
            }
            const size_t vb = (size_t)b * CV * NPIX + jt * BJ;
            for (int it = tx; it < 1024; it += 128) {
                int row = it >> 2, ch = it & 3;
                uint32_t d = (uint32_t)row * RV + ch * 16;
                size_t s = vb + (size_t)row * NPIX + ch * 8;
                *(uint4*)(smem + SVH + d) = *(const uint4*)(Vhi + s);
                *(uint4*)(smem + SVL + d) = *(const uint4*)(Vlo + s);
            }
        }
        __syncthreads();

        // ---- S = Q·K^T, 3-term bf16 split ----
        float S[4][4];
#pragma unroll
        for (int nb = 0; nb < 4; nb++)
#pragma unroll
            for (int e = 0; e < 4; e++) S[nb][e] = 0.0f;

#pragma unroll
        for (int s = 0; s < 8; s++) {
            uint32_t qh[4], ql[4];
            ldsm4(qh, aQ + s * 32);
            ldsm4(ql, aQ + (SQL - SQH) + s * 32);
#pragma unroll
            for (int jb2 = 0; jb2 < 2; jb2++) {
                uint32_t kh[4], kl[4];
                uint32_t ka = aK + (uint32_t)jb2 * (16 * RQK) + s * 32;
                ldsm4(kh, ka);
                ldsm4(kl, ka + (SKL - SKH));
                mma_bf16(S[2 * jb2],     qh, kh[0], kh[1]);
                mma_bf16(S[2 * jb2 + 1], qh, kh[2], kh[3]);
                mma_bf16(S[2 * jb2],     qh, kl[0], kl[1]);
                mma_bf16(S[2 * jb2 + 1], qh, kl[2], kl[3]);
                mma_bf16(S[2 * jb2],     ql, kh[0], kh[1]);
                mma_bf16(S[2 * jb2 + 1], ql, kh[2], kh[3]);
            }
        }

        // ---- softmax (no max-sub) + in-register P pack (hi trunc / lo resid) ----
        uint32_t Ph[2][4], Pl[2][4];
#pragma unroll
        for (int nb = 0; nb < 4; nb++) {
            float p0 = exp2_fast(S[nb][0]);
            float p1 = exp2_fast(S[nb][1]);
            float p2 = exp2_fast(S[nb][2]);
            float p3 = exp2_fast(S[nb][3]);
            L0 += p0 + p1; L1 += p2 + p3;
            uint32_t u0 = __float_as_uint(p0), u1 = __float_as_uint(p1);
            uint32_t u2 = __float_as_uint(p2), u3 = __float_as_uint(p3);
            float l0 = p0 - __uint_as_float(u0 & 0xFFFF0000u);
            float l1 = p1 - __uint_as_float(u1 & 0xFFFF0000u);
            float l2 = p2 - __uint_as_float(u2 & 0xFFFF0000u);
            float l3 = p3 - __uint_as_float(u3 & 0xFFFF0000u);
            int m = nb >> 1, sl = (nb & 1) * 2;
            Ph[m][sl]     = __byte_perm(u0, u1, 0x7632);
            Ph[m][sl + 1] = __byte_perm(u2, u3, 0x7632);
            uint32_t a, c;
            asm("cvt.rn.bf16x2.f32 %0, %1, %2;" : "=r"(a) : "f"(l1), "f"(l0));
            asm("cvt.rn.bf16x2.f32 %0, %1, %2;" : "=r"(c) : "f"(l3), "f"(l2));
            Pl[m][sl] = a; Pl[m][sl + 1] = c;
        }

        // ---- D += P·V^T, 3-term split ----
#pragma unroll
        for (int m = 0; m < 2; m++) {
#pragma unroll
            for (int cb2 = 0; cb2 < 16; cb2++) {
                uint32_t vh[4], vl[4];
                uint32_t va = aV + (uint32_t)cb2 * (16 * RV) + m * 32;
                ldsm4(vh, va);
                ldsm4(vl, va + (SVL - SVH));
                mma_bf16(D[2 * cb2],     Ph[m], vh[0], vh[1]);
                mma_bf16(D[2 * cb2 + 1], Ph[m], vh[2], vh[3]);
                mma_bf16(D[2 * cb2],     Ph[m], vl[0], vl[1]);
                mma_bf16(D[2 * cb2 + 1], Ph[m], vl[2], vl[3]);
                mma_bf16(D[2 * cb2],     Pl[m], vh[0], vh[1]);
                mma_bf16(D[2 * cb2 + 1], Pl[m], vh[2], vh[3]);
            }
        }
    }

    // ---- epilogue: reduce L over quad, normalize, fused writes ----
    L0 += __shfl_xor_sync(0xffffffffu, L0, 1);
    L0 += __shfl_xor_sync(0xffffffffu, L0, 2);
    L1 += __shfl_xor_sync(0xffffffffu, L1, 1);
    L1 += __shfl_xor_sync(0xffffffffu, L1, 2);
    const float inv0 = 1.0f / L0, inv1 = 1.0f / L1;
    const int ig0 = i0 + wid * 16 + g, ig8 = ig0 + 8;
    float* attn = out + (size_t)BATCH * CV * NPIX;
#pragma unroll
    for (int nb = 0; nb < 32; nb++) {
        int c = 8 * nb + 2 * t;
        size_t g0 = ((size_t)b * CV + c) * NPIX;
        float v00 = D[nb][0] * inv0, v01 = D[nb][1] * inv0;
        float v10 = D[nb][2] * inv1, v11 = D[nb][3] * inv1;
        out[g0 + ig0] = v00 * motion[g0 + ig0];               attn[g0 + ig0] = v00;
        out[g0 + NPIX + ig0] = v01 * motion[g0 + NPIX + ig0]; attn[g0 + NPIX + ig0] = v01;
        out[g0 + ig8] = v10 * motion[g0 + ig8];               attn[g0 + ig8] = v10;
        out[g0 + NPIX + ig8] = v11 * motion[g0 + NPIX + ig8]; attn[g0 + NPIX + ig8] = v11;
    }
}

// ============================================================================
extern "C" void kernel_launch(void* const* d_in, const int* in_sizes, int n_in,
                              void* d_out, int out_size)
{
    const float* a1  = (const float*)d_in[0];
    const float* a2  = (const float*)d_in[1];
    const float* mot = (const float*)d_in[2];
    const float* Wq  = (const float*)d_in[3];
    const float* bq  = (const float*)d_in[4];
    const float* Wk  = (const float*)d_in[5];
    const float* bk  = (const float*)d_in[6];
    const float* Wv  = (const float*)d_in[7];
    const float* bv  = (const float*)d_in[8];
    float* out = (float*)d_out;

    __nv_bfloat16 *Qh, *Ql, *Kh, *Kl, *Vh, *Vl;
    cudaGetSymbolAddress((void**)&Qh, g_Qhi);  cudaGetSymbolAddress((void**)&Ql, g_Qlo);
    cudaGetSymbolAddress((void**)&Kh, g_Khi);  cudaGetSymbolAddress((void**)&Kl, g_Klo);
    cudaGetSymbolAddress((void**)&Vh, g_Vthi); cudaGetSymbolAddress((void**)&Vl, g_Vtlo);

    const float LOG2E = 1.4426950408889634f;

    proj_split<CQK, CQK, false><<<dim3(NPIX / 64, 2, BATCH), 256>>>(a2, Wq, bq, Qh, Ql, LOG2E);
    proj_split<CQK, CQK, false><<<dim3(NPIX / 64, 2, BATCH), 256>>>(a1, Wk, bk, Kh, Kl, 1.0f);
    proj_split<CV,  CV,  true ><<<dim3(NPIX / 64, 4, BATCH), 256>>>(mot, Wv, bv, Vh, Vl, 1.0f);

    cudaFuncSetAttribute(flash_hmma, cudaFuncAttributeMaxDynamicSharedMemorySize, SMTOT);
    flash_hmma<<<dim3(NPIX / 64, BATCH), 128, SMTOT>>>(Qh, Ql, Kh, Kl, Vh, Vl, mot, out);
}

// round 16
// speedup vs baseline: 1.1751x; 1.1751x over previous
#include <cuda_runtime.h>
#include <cuda_bf16.h>
#include <cstdint>

#define BATCH 8
#define NPIX  4096
#define CQK   128
#define CV    256
#define BJ    64

__device__ __nv_bfloat16 g_Qhi[BATCH * NPIX * CQK];
__device__ __nv_bfloat16 g_Qlo[BATCH * NPIX * CQK];
__device__ __nv_bfloat16 g_Khi[BATCH * NPIX * CQK];
__device__ __nv_bfloat16 g_Klo[BATCH * NPIX * CQK];
__device__ __nv_bfloat16 g_Vthi[BATCH * CV * NPIX];  // [b][c][n] transposed
__device__ __nv_bfloat16 g_Vtlo[BATCH * CV * NPIX];

__device__ __forceinline__ uint32_t smem_u32(const void* p) {
    uint32_t a;
    asm("{ .reg .u64 t; cvta.to.shared.u64 t, %1; cvt.u32.u64 %0, t; }" : "=r"(a) : "l"(p));
    return a;
}
__device__ __forceinline__ void ldsm4(uint32_t r[4], uint32_t addr) {
    asm volatile("ldmatrix.sync.aligned.m8n8.x4.shared.b16 {%0,%1,%2,%3}, [%4];"
                 : "=r"(r[0]), "=r"(r[1]), "=r"(r[2]), "=r"(r[3]) : "r"(addr));
}
__device__ __forceinline__ void mma_bf16(float d[4], const uint32_t a[4],
                                         uint32_t b0, uint32_t b1) {
    asm("mma.sync.aligned.m16n8k16.row.col.f32.bf16.bf16.f32 "
        "{%0,%1,%2,%3}, {%4,%5,%6,%7}, {%8,%9}, {%0,%1,%2,%3};"
        : "+f"(d[0]), "+f"(d[1]), "+f"(d[2]), "+f"(d[3])
        : "r"(a[0]), "r"(a[1]), "r"(a[2]), "r"(a[3]), "r"(b0), "r"(b1));
}
__device__ __forceinline__ void cp16(uint32_t dst, const void* src) {
    asm volatile("cp.async.cg.shared.global [%0], [%1], 16;" :: "r"(dst), "l"(src));
}
#define CP_COMMIT() asm volatile("cp.async.commit_group;" ::: "memory")
#define CP_WAIT(n)  asm volatile("cp.async.wait_group %0;" :: "n"(n) : "memory")

__device__ __forceinline__ float exp2_fast(float x) {
    x = fmaxf(x, -126.0f);
    float fl = floorf(x), f = x - fl;
    float p = 1.87757667e-3f;
    p = fmaf(p, f, 8.98934058e-3f); p = fmaf(p, f, 5.58263180e-2f);
    p = fmaf(p, f, 2.40153617e-1f); p = fmaf(p, f, 6.93153073e-1f);
    p = fmaf(p, f, 9.99999994e-1f);
    return p * __int_as_float(((int)fl + 127) << 23);
}

// ============================================================================
// Projection -> bf16 hi/lo split. TR=false: [b][i][o]; TR=true: [b][o][i].
// ============================================================================
template<int CIN, int COUT, bool TR>
__global__ __launch_bounds__(256) void proj_split(
    const float* __restrict__ in, const float* __restrict__ W,
    const float* __restrict__ bias, __nv_bfloat16* __restrict__ ohi,
    __nv_bfloat16* __restrict__ olo, float scale)
{
    __shared__ float sIn[32][64], sWT[32][64], sOut[64][68];
    const int b = blockIdx.z, i0 = blockIdx.x * 64, o0 = blockIdx.y * 64;
    const int tx = threadIdx.x, ti = tx & 15, to = tx >> 4;
    const float* inb = in + (size_t)b * CIN * NPIX + i0;

    float acc[4][4];
#pragma unroll
    for (int a = 0; a < 4; a++)
#pragma unroll
        for (int c = 0; c < 4; c++) acc[a][c] = 0.0f;

    for (int k0 = 0; k0 < CIN; k0 += 32) {
        for (int t = tx; t < 512; t += 256) {
            int k = t >> 4, i4 = (t & 15) << 2;
            *(float4*)&sIn[k][i4] = *(const float4*)&inb[(size_t)(k0 + k) * NPIX + i4];
        }
        for (int t = tx; t < 512; t += 256) {
            int o = t >> 3, k4 = (t & 7) << 2;
            float4 w = *(const float4*)&W[(size_t)(o0 + o) * CIN + k0 + k4];
            sWT[k4][o] = w.x; sWT[k4 + 1][o] = w.y; sWT[k4 + 2][o] = w.z; sWT[k4 + 3][o] = w.w;
        }
        __syncthreads();
#pragma unroll
        for (int k = 0; k < 32; k++) {
            float4 a = *(float4*)&sIn[k][ti * 4];
            float4 w = *(float4*)&sWT[k][to * 4];
            float av[4] = {a.x, a.y, a.z, a.w}, wv[4] = {w.x, w.y, w.z, w.w};
#pragma unroll
            for (int ii = 0; ii < 4; ii++)
#pragma unroll
                for (int oo = 0; oo < 4; oo++)
                    acc[ii][oo] = fmaf(av[ii], wv[oo], acc[ii][oo]);
        }
        __syncthreads();
    }
#pragma unroll
    for (int ii = 0; ii < 4; ii++)
#pragma unroll
        for (int oo = 0; oo < 4; oo++)
            sOut[ti * 4 + ii][to * 4 + oo] = acc[ii][oo];
    __syncthreads();

    for (int t = tx; t < 1024; t += 256) {
        float x[4];
        size_t g;
        if (!TR) {
            int i = t >> 4, o4 = (t & 15) << 2;
            float4 v = *(float4*)&sOut[i][o4];
            float4 bb = *(const float4*)&bias[o0 + o4];
            x[0] = (v.x + bb.x) * scale; x[1] = (v.y + bb.y) * scale;
            x[2] = (v.z + bb.z) * scale; x[3] = (v.w + bb.w) * scale;
            g = ((size_t)b * NPIX + i0 + i) * COUT + o0 + o4;
        } else {
            int o = t >> 4, i4 = (t & 15) << 2;
            float bb = bias[o0 + o];
#pragma unroll
            for (int e = 0; e < 4; e++) x[e] = (sOut[i4 + e][o] + bb) * scale;
            g = ((size_t)b * COUT + o0 + o) * NPIX + i0 + i4;
        }
#pragma unroll
        for (int e = 0; e < 4; e++) {
            __nv_bfloat16 h = __float2bfloat16_rn(x[e]);
            ohi[g + e] = h;
            olo[g + e] = __float2bfloat16_rn(x[e] - __bfloat162float(h));
        }
    }
}

// ============================================================================
// HMMA flash attention + fuse — R13 shape (256 thr / 8 warps / 128 rows / BJ=64)
// + cp.async pipeline: K double-buffered (prefetch t+1 during t), V fill
// hidden under QK+softmax. smem 208 KB.
// Q/K rows: 256B data, stride 272B. Vt rows: 128B data, stride 144B.
// ============================================================================
#define RQK 272
#define RV  144
#define SQH 0
#define SQL 34816
#define SKB 69632        // K stages: SKB + stage*34816 (hi), +17408 (lo)
#define KSTG 34816
#define SVH 139264
#define SVL 176128
#define SMTOT 212992

__global__ __launch_bounds__(256, 1) void flash_hmma(
    const __nv_bfloat16* __restrict__ Qhi, const __nv_bfloat16* __restrict__ Qlo,
    const __nv_bfloat16* __restrict__ Khi, const __nv_bfloat16* __restrict__ Klo,
    const __nv_bfloat16* __restrict__ Vhi, const __nv_bfloat16* __restrict__ Vlo,
    const float* __restrict__ motion, float* __restrict__ out)
{
    extern __shared__ char smem[];
    const uint32_t sb = smem_u32(smem);
    const int tx = threadIdx.x, wid = tx >> 5, lane = tx & 31;
    const int b = blockIdx.y, i0 = blockIdx.x * 128;
    const int g = lane >> 2, t = lane & 3;
    const int mr = lane >> 3, rr = lane & 7;   // ldmatrix role: matrix idx, row

    const uint32_t aQ = sb + SQH + (uint32_t)(wid * 16 + rr + (mr & 1) * 8) * RQK + (mr >> 1) * 16;
    const uint32_t kloff = (uint32_t)(rr + (mr >> 1) * 8) * RQK + (mr & 1) * 16;
    const uint32_t aV = sb + SVH + (uint32_t)(rr + (mr >> 1) * 8) * RV + (mr & 1) * 16;

    // prologue: prefetch K[0] (group B_{-1}), fill Q with plain loads
    {
        const size_t kb = (size_t)b * NPIX * CQK;
        const uint32_t kdst = sb + SKB;
        for (int it = tx; it < 1024; it += 256) {
            int row = it >> 4, ch = it & 15;
            uint32_t d = (uint32_t)row * RQK + ch * 16;
            size_t s = kb + (size_t)row * CQK + ch * 8;
            cp16(kdst + d, Khi + s);
            cp16(kdst + KSTG / 2 + d, Klo + s);
        }
        CP_COMMIT();
        const size_t qb = ((size_t)b * NPIX + i0) * CQK;
        for (int it = tx; it < 2048; it += 256) {
            int row = it >> 4, ch = it & 15;
            uint32_t d = (uint32_t)row * RQK + ch * 16;
            size_t s = qb + (size_t)row * CQK + ch * 8;
            *(uint4*)(smem + SQH + d) = *(const uint4*)(Qhi + s);
            *(uint4*)(smem + SQL + d) = *(const uint4*)(Qlo + s);
        }
    }

    float D[32][4];
#pragma unroll
    for (int nb = 0; nb < 32; nb++)
#pragma unroll
        for (int e = 0; e < 4; e++) D[nb][e] = 0.0f;
    float L0 = 0.0f, L1 = 0.0f;

    for (int jt = 0; jt < NPIX / BJ; jt++) {
        // issue V[jt] (group A)
        {
            const size_t vb = (size_t)b * CV * NPIX + jt * BJ;
            for (int it = tx; it < 2048; it += 256) {
                int row = it >> 3, ch = it & 7;
                uint32_t d = (uint32_t)row * RV + ch * 16;
                size_t s = vb + (size_t)row * NPIX + ch * 8;
                cp16(sb + SVH + d, Vhi + s);
                cp16(sb + SVL + d, Vlo + s);
            }
            CP_COMMIT();
        }
        // prefetch K[jt+1] into other stage (group B); wraps on last tile
        {
            const int jn = (jt + 1) & (NPIX / BJ - 1);
            const size_t kb = ((size_t)b * NPIX + jn * BJ) * CQK;
            const uint32_t kdst = sb + SKB + (uint32_t)((jt + 1) & 1) * KSTG;
            for (int it = tx; it < 1024; it += 256) {
                int row = it >> 4, ch = it & 15;
                uint32_t d = (uint32_t)row * RQK + ch * 16;
                size_t s = kb + (size_t)row * CQK + ch * 8;
                cp16(kdst + d, Khi + s);
                cp16(kdst + KSTG / 2 + d, Klo + s);
            }
            CP_COMMIT();
        }
        CP_WAIT(2);        // K[jt] landed
        __syncthreads();

        const uint32_t aK = sb + SKB + (uint32_t)(jt & 1) * KSTG + kloff;

        // ---- S = Q·K^T, 3-term bf16 split ----
        float S[8][4];
#pragma unroll
        for (int nb = 0; nb < 8; nb++)
#pragma unroll
            for (int e = 0; e < 4; e++) S[nb][e] = 0.0f;

#pragma unroll
        for (int s = 0; s < 8; s++) {
            uint32_t qh[4], ql[4];
            ldsm4(qh, aQ + s * 32);
            ldsm4(ql, aQ + (SQL - SQH) + s * 32);
#pragma unroll
            for (int jb2 = 0; jb2 < 4; jb2++) {
                uint32_t kh[4], kl[4];
                uint32_t ka = aK + (uint32_t)jb2 * (16 * RQK) + s * 32;
                ldsm4(kh, ka);
                ldsm4(kl, ka + KSTG / 2);
                mma_bf16(S[2 * jb2],     qh, kh[0], kh[1]);
                mma_bf16(S[2 * jb2 + 1], qh, kh[2], kh[3]);
                mma_bf16(S[2 * jb2],     qh, kl[0], kl[1]);
                mma_bf16(S[2 * jb2 + 1], qh, kl[2], kl[3]);
                mma_bf16(S[2 * jb2],     ql, kh[0], kh[1]);
                mma_bf16(S[2 * jb2 + 1], ql, kh[2], kh[3]);
            }
        }

        // ---- softmax (no max-sub) + in-register P pack (hi trunc / lo resid) ----
        uint32_t Ph[4][4], Pl[4][4];
#pragma unroll
        for (int nb = 0; nb < 8; nb++) {
            float p0 = exp2_fast(S[nb][0]);
            float p1 = exp2_fast(S[nb][1]);
            float p2 = exp2_fast(S[nb][2]);
            float p3 = exp2_fast(S[nb][3]);
            L0 += p0 + p1; L1 += p2 + p3;
            uint32_t u0 = __float_as_uint(p0), u1 = __float_as_uint(p1);
            uint32_t u2 = __float_as_uint(p2), u3 = __float_as_uint(p3);
            float l0 = p0 - __uint_as_float(u0 & 0xFFFF0000u);
            float l1 = p1 - __uint_as_float(u1 & 0xFFFF0000u);
            float l2 = p2 - __uint_as_float(u2 & 0xFFFF0000u);
            float l3 = p3 - __uint_as_float(u3 & 0xFFFF0000u);
            int m = nb >> 1, sl = (nb & 1) * 2;
            Ph[m][sl]     = __byte_perm(u0, u1, 0x7632);
            Ph[m][sl + 1] = __byte_perm(u2, u3, 0x7632);
            uint32_t a, c;
            asm("cvt.rn.bf16x2.f32 %0, %1, %2;" : "=r"(a) : "f"(l1), "f"(l0));
            asm("cvt.rn.bf16x2.f32 %0, %1, %2;" : "=r"(c) : "f"(l3), "f"(l2));
            Pl[m][sl] = a; Pl[m][sl + 1] = c;
        }

        CP_WAIT(1);        // V[jt] landed (K[jt+1] may still be in flight)
        __syncthreads();

        // ---- D += P·V^T, 3-term split ----
#pragma unroll
        for (int m = 0; m < 4; m++) {
#pragma unroll
            for (int cb2 = 0; cb2 < 16; cb2++) {
                uint32_t vh[4], vl[4];
                uint32_t va = aV + (uint32_t)cb2 * (16 * RV) + m * 32;
                ldsm4(vh, va);
                ldsm4(vl, va + (SVL - SVH));
                mma_bf16(D[2 * cb2],     Ph[m], vh[0], vh[1]);
                mma_bf16(D[2 * cb2 + 1], Ph[m], vh[2], vh[3]);
                mma_bf16(D[2 * cb2],     Ph[m], vl[0], vl[1]);
                mma_bf16(D[2 * cb2 + 1], Ph[m], vl[2], vl[3]);
                mma_bf16(D[2 * cb2],     Pl[m], vh[0], vh[1]);
                mma_bf16(D[2 * cb2 + 1], Pl[m], vh[2], vh[3]);
            }
        }
        __syncthreads();   // V buffer free for next tile's issue
    }

    // ---- epilogue: reduce L over quad, normalize, fused writes ----
    L0 += __shfl_xor_sync(0xffffffffu, L0, 1);
    L0 += __shfl_xor_sync(0xffffffffu, L0, 2);
    L1 += __shfl_xor_sync(0xffffffffu, L1, 1);
    L1 += __shfl_xor_sync(0xffffffffu, L1, 2);
    const float inv0 = 1.0f / L0, inv1 = 1.0f / L1;
    const int ig0 = i0 + wid * 16 + g, ig8 = ig0 + 8;
    float* attn = out + (size_t)BATCH * CV * NPIX;
#pragma unroll
    for (int nb = 0; nb < 32; nb++) {
        int c = 8 * nb + 2 * t;
        size_t g0 = ((size_t)b * CV + c) * NPIX;
        float v00 = D[nb][0] * inv0, v01 = D[nb][1] * inv0;
        float v10 = D[nb][2] * inv1, v11 = D[nb][3] * inv1;
        out[g0 + ig0] = v00 * motion[g0 + ig0];               attn[g0 + ig0] = v00;
        out[g0 + NPIX + ig0] = v01 * motion[g0 + NPIX + ig0]; attn[g0 + NPIX + ig0] = v01;
        out[g0 + ig8] = v10 * motion[g0 + ig8];               attn[g0 + ig8] = v10;
        out[g0 + NPIX + ig8] = v11 * motion[g0 + NPIX + ig8]; attn[g0 + NPIX + ig8] = v11;
    }
}

// ============================================================================
extern "C" void kernel_launch(void* const* d_in, const int* in_sizes, int n_in,
                              void* d_out, int out_size)
{
    const float* a1  = (const float*)d_in[0];
    const float* a2  = (const float*)d_in[1];
    const float* mot = (const float*)d_in[2];
    const float* Wq  = (const float*)d_in[3];
    const float* bq  = (const float*)d_in[4];
    const float* Wk  = (const float*)d_in[5];
    const float* bk  = (const float*)d_in[6];
    const float* Wv  = (const float*)d_in[7];
    const float* bv  = (const float*)d_in[8];
    float* out = (float*)d_out;

    __nv_bfloat16 *Qh, *Ql, *Kh, *Kl, *Vh, *Vl;
    cudaGetSymbolAddress((void**)&Qh, g_Qhi);  cudaGetSymbolAddress((void**)&Ql, g_Qlo);
    cudaGetSymbolAddress((void**)&Kh, g_Khi);  cudaGetSymbolAddress((void**)&Kl, g_Klo);
    cudaGetSymbolAddress((void**)&Vh, g_Vthi); cudaGetSymbolAddress((void**)&Vl, g_Vtlo);

    const float LOG2E = 1.4426950408889634f;

    proj_split<CQK, CQK, false><<<dim3(NPIX / 64, 2, BATCH), 256>>>(a2, Wq, bq, Qh, Ql, LOG2E);
    proj_split<CQK, CQK, false><<<dim3(NPIX / 64, 2, BATCH), 256>>>(a1, Wk, bk, Kh, Kl, 1.0f);
    proj_split<CV,  CV,  true ><<<dim3(NPIX / 64, 4, BATCH), 256>>>(mot, Wv, bv, Vh, Vl, 1.0f);

    cudaFuncSetAttribute(flash_hmma, cudaFuncAttributeMaxDynamicSharedMemorySize, SMTOT);
    flash_hmma<<<dim3(NPIX / 128, BATCH), 256, SMTOT>>>(Qh, Ql, Kh, Kl, Vh, Vl, mot, out);
}

// round 17
// speedup vs baseline: 2.1010x; 1.7879x over previous
#include <cuda_runtime.h>
#include <cuda_bf16.h>
#include <cstdint>

#define BATCH 8
#define NPIX  4096
#define CQK   128
#define CV    256
#define BJ    64

__device__ __nv_bfloat16 g_Qhi[BATCH * NPIX * CQK];
__device__ __nv_bfloat16 g_Qlo[BATCH * NPIX * CQK];
__device__ __nv_bfloat16 g_Khi[BATCH * NPIX * CQK];
__device__ __nv_bfloat16 g_Klo[BATCH * NPIX * CQK];
__device__ __nv_bfloat16 g_Vthi[BATCH * CV * NPIX];  // [b][c][n] transposed
__device__ __nv_bfloat16 g_Vtlo[BATCH * CV * NPIX];

__device__ __forceinline__ uint32_t smem_u32(const void* p) {
    uint32_t a;
    asm("{ .reg .u64 t; cvta.to.shared.u64 t, %1; cvt.u32.u64 %0, t; }" : "=r"(a) : "l"(p));
    return a;
}
__device__ __forceinline__ void ldsm4(uint32_t r[4], uint32_t addr) {
    asm volatile("ldmatrix.sync.aligned.m8n8.x4.shared.b16 {%0,%1,%2,%3}, [%4];"
                 : "=r"(r[0]), "=r"(r[1]), "=r"(r[2]), "=r"(r[3]) : "r"(addr));
}
__device__ __forceinline__ void mma_bf16(float d[4], const uint32_t a[4],
                                         uint32_t b0, uint32_t b1) {
    asm("mma.sync.aligned.m16n8k16.row.col.f32.bf16.bf16.f32 "
        "{%0,%1,%2,%3}, {%4,%5,%6,%7}, {%8,%9}, {%0,%1,%2,%3};"
        : "+f"(d[0]), "+f"(d[1]), "+f"(d[2]), "+f"(d[3])
        : "r"(a[0]), "r"(a[1]), "r"(a[2]), "r"(a[3]), "r"(b0), "r"(b1));
}
__device__ __forceinline__ void cp16(uint32_t dst, const void* src) {
    asm volatile("cp.async.cg.shared.global [%0], [%1], 16;" :: "r"(dst), "l"(src));
}
#define CP_COMMIT() asm volatile("cp.async.commit_group;" ::: "memory")
#define CP_WAIT(n)  asm volatile("cp.async.wait_group %0;" :: "n"(n) : "memory")

__device__ __forceinline__ float exp2_fast(float x) {
    x = fmaxf(x, -126.0f);
    float fl = floorf(x), f = x - fl;
    float p = 1.87757667e-3f;
    p = fmaf(p, f, 8.98934058e-3f); p = fmaf(p, f, 5.58263180e-2f);
    p = fmaf(p, f, 2.40153617e-1f); p = fmaf(p, f, 6.93153073e-1f);
    p = fmaf(p, f, 9.99999994e-1f);
    return p * __int_as_float(((int)fl + 127) << 23);
}

// ============================================================================
// Projection -> bf16 hi/lo split. TR=false: [b][i][o]; TR=true: [b][o][i].
// ============================================================================
template<int CIN, int COUT, bool TR>
__global__ __launch_bounds__(256) void proj_split(
    const float* __restrict__ in, const float* __restrict__ W,
    const float* __restrict__ bias, __nv_bfloat16* __restrict__ ohi,
    __nv_bfloat16* __restrict__ olo, float scale)
{
    __shared__ float sIn[32][64], sWT[32][64], sOut[64][68];
    const int b = blockIdx.z, i0 = blockIdx.x * 64, o0 = blockIdx.y * 64;
    const int tx = threadIdx.x, ti = tx & 15, to = tx >> 4;
    const float* inb = in + (size_t)b * CIN * NPIX + i0;

    float acc[4][4];
#pragma unroll
    for (int a = 0; a < 4; a++)
#pragma unroll
        for (int c = 0; c < 4; c++) acc[a][c] = 0.0f;

    for (int k0 = 0; k0 < CIN; k0 += 32) {
        for (int t = tx; t < 512; t += 256) {
            int k = t >> 4, i4 = (t & 15) << 2;
            *(float4*)&sIn[k][i4] = *(const float4*)&inb[(size_t)(k0 + k) * NPIX + i4];
        }
        for (int t = tx; t < 512; t += 256) {
            int o = t >> 3, k4 = (t & 7) << 2;
            float4 w = *(const float4*)&W[(size_t)(o0 + o) * CIN + k0 + k4];
            sWT[k4][o] = w.x; sWT[k4 + 1][o] = w.y; sWT[k4 + 2][o] = w.z; sWT[k4 + 3][o] = w.w;
        }
        __syncthreads();
#pragma unroll
        for (int k = 0; k < 32; k++) {
            float4 a = *(float4*)&sIn[k][ti * 4];
            float4 w = *(float4*)&sWT[k][to * 4];
            float av[4] = {a.x, a.y, a.z, a.w}, wv[4] = {w.x, w.y, w.z, w.w};
#pragma unroll
            for (int ii = 0; ii < 4; ii++)
#pragma unroll
                for (int oo = 0; oo < 4; oo++)
                    acc[ii][oo] = fmaf(av[ii], wv[oo], acc[ii][oo]);
        }
        __syncthreads();
    }
#pragma unroll
    for (int ii = 0; ii < 4; ii++)
#pragma unroll
        for (int oo = 0; oo < 4; oo++)
            sOut[ti * 4 + ii][to * 4 + oo] = acc[ii][oo];
    __syncthreads();

    for (int t = tx; t < 1024; t += 256) {
        float x[4];
        size_t g;
        if (!TR) {
            int i = t >> 4, o4 = (t & 15) << 2;
            float4 v = *(float4*)&sOut[i][o4];
            float4 bb = *(const float4*)&bias[o0 + o4];
            x[0] = (v.x + bb.x) * scale; x[1] = (v.y + bb.y) * scale;
            x[2] = (v.z + bb.z) * scale; x[3] = (v.w + bb.w) * scale;
            g = ((size_t)b * NPIX + i0 + i) * COUT + o0 + o4;
        } else {
            int o = t >> 4, i4 = (t & 15) << 2;
            float bb = bias[o0 + o];
#pragma unroll
            for (int e = 0; e < 4; e++) x[e] = (sOut[i4 + e][o] + bb) * scale;
            g = ((size_t)b * COUT + o0 + o) * NPIX + i0 + i4;
        }
#pragma unroll
        for (int e = 0; e < 4; e++) {
            __nv_bfloat16 h = __float2bfloat16_rn(x[e]);
            ohi[g + e] = h;
            olo[g + e] = __float2bfloat16_rn(x[e] - __bfloat162float(h));
        }
    }
}

// ============================================================================
// HMMA flash attention + fuse — 256 thr / 8 warps / 128 rows / BJ=64,
// cp.async pipeline: Q + K[0] prefetched in prologue, K double-buffered
// (prefetch t+1 during t), V fill hidden under QK+softmax. smem 208 KB.
// ============================================================================
#define RQK 272
#define RV  144
#define SQH 0
#define SQL 34816
#define SKB 69632        // K stages: SKB + stage*34816 (hi), +17408 (lo)
#define KSTG 34816
#define SVH 139264
#define SVL 176128
#define SMTOT 212992

__global__ __launch_bounds__(256, 1) void flash_hmma(
    const __nv_bfloat16* __restrict__ Qhi, const __nv_bfloat16* __restrict__ Qlo,
    const __nv_bfloat16* __restrict__ Khi, const __nv_bfloat16* __restrict__ Klo,
    const __nv_bfloat16* __restrict__ Vhi, const __nv_bfloat16* __restrict__ Vlo,
    const float* __restrict__ motion, float* __restrict__ out)
{
    extern __shared__ char smem[];
    const uint32_t sb = smem_u32(smem);
    const int tx = threadIdx.x, wid = tx >> 5, lane = tx & 31;
    const int b = blockIdx.y, i0 = blockIdx.x * 128;
    const int g = lane >> 2, t = lane & 3;
    const int mr = lane >> 3, rr = lane & 7;   // ldmatrix role: matrix idx, row

    const uint32_t aQ = sb + SQH + (uint32_t)(wid * 16 + rr + (mr & 1) * 8) * RQK + (mr >> 1) * 16;
    const uint32_t kloff = (uint32_t)(rr + (mr >> 1) * 8) * RQK + (mr & 1) * 16;
    const uint32_t aV = sb + SVH + (uint32_t)(rr + (mr >> 1) * 8) * RV + (mr & 1) * 16;

    // prologue: cp.async Q (group 0), then cp.async K[0] (group 1)
    {
        const size_t qb = ((size_t)b * NPIX + i0) * CQK;
        for (int it = tx; it < 2048; it += 256) {
            int row = it >> 4, ch = it & 15;
            uint32_t d = (uint32_t)row * RQK + ch * 16;
            size_t s = qb + (size_t)row * CQK + ch * 8;
            cp16(sb + SQH + d, Qhi + s);
            cp16(sb + SQL + d, Qlo + s);
        }
        CP_COMMIT();
        const size_t kb = (size_t)b * NPIX * CQK;
        const uint32_t kdst = sb + SKB;
        for (int it = tx; it < 1024; it += 256) {
            int row = it >> 4, ch = it & 15;
            uint32_t d = (uint32_t)row * RQK + ch * 16;
            size_t s = kb + (size_t)row * CQK + ch * 8;
            cp16(kdst + d, Khi + s);
            cp16(kdst + KSTG / 2 + d, Klo + s);
        }
        CP_COMMIT();
    }

    float D[32][4];
#pragma unroll
    for (int nb = 0; nb < 32; nb++)
#pragma unroll
        for (int e = 0; e < 4; e++) D[nb][e] = 0.0f;
    float L0 = 0.0f, L1 = 0.0f;

    for (int jt = 0; jt < NPIX / BJ; jt++) {
        // issue V[jt]
        {
            const size_t vb = (size_t)b * CV * NPIX + jt * BJ;
            for (int it = tx; it < 2048; it += 256) {
                int row = it >> 3, ch = it & 7;
                uint32_t d = (uint32_t)row * RV + ch * 16;
                size_t s = vb + (size_t)row * NPIX + ch * 8;
                cp16(sb + SVH + d, Vhi + s);
                cp16(sb + SVL + d, Vlo + s);
            }
            CP_COMMIT();
        }
        // prefetch K[jt+1] into other stage; wraps on last tile
        {
            const int jn = (jt + 1) & (NPIX / BJ - 1);
            const size_t kb = ((size_t)b * NPIX + jn * BJ) * CQK;
            const uint32_t kdst = sb + SKB + (uint32_t)((jt + 1) & 1) * KSTG;
            for (int it = tx; it < 1024; it += 256) {
                int row = it >> 4, ch = it & 15;
                uint32_t d = (uint32_t)row * RQK + ch * 16;
                size_t s = kb + (size_t)row * CQK + ch * 8;
                cp16(kdst + d, Khi + s);
                cp16(kdst + KSTG / 2 + d, Klo + s);
            }
            CP_COMMIT();
        }
        CP_WAIT(2);        // jt=0: Q + K[0] landed; jt>0: K[jt] landed
        __syncthreads();

        const uint32_t aK = sb + SKB + (uint32_t)(jt & 1) * KSTG + kloff;

        // ---- S = Q·K^T, 3-term bf16 split ----
        float S[8][4];
#pragma unroll
        for (int nb = 0; nb < 8; nb++)
#pragma unroll
            for (int e = 0; e < 4; e++) S[nb][e] = 0.0f;

#pragma unroll
        for (int s = 0; s < 8; s++) {
            uint32_t qh[4], ql[4];
            ldsm4(qh, aQ + s * 32);
            ldsm4(ql, aQ + (SQL - SQH) + s * 32);
#pragma unroll
            for (int jb2 = 0; jb2 < 4; jb2++) {
                uint32_t kh[4], kl[4];
                uint32_t ka = aK + (uint32_t)jb2 * (16 * RQK) + s * 32;
                ldsm4(kh, ka);
                ldsm4(kl, ka + KSTG / 2);
                mma_bf16(S[2 * jb2],     qh, kh[0], kh[1]);
                mma_bf16(S[2 * jb2 + 1], qh, kh[2], kh[3]);
                mma_bf16(S[2 * jb2],     qh, kl[0], kl[1]);
                mma_bf16(S[2 * jb2 + 1], qh, kl[2], kl[3]);
                mma_bf16(S[2 * jb2],     ql, kh[0], kh[1]);
                mma_bf16(S[2 * jb2 + 1], ql, kh[2], kh[3]);
            }
        }

        // ---- softmax (no max-sub) + in-register P pack (hi trunc / lo resid) ----
        uint32_t Ph[4][4], Pl[4][4];
#pragma unroll
        for (int nb = 0; nb < 8; nb++) {
            float p0 = exp2_fast(S[nb][0]);
            float p1 = exp2_fast(S[nb][1]);
            float p2 = exp2_fast(S[nb][2]);
            float p3 = exp2_fast(S[nb][3]);
            L0 += p0 + p1; L1 += p2 + p3;
            uint32_t u0 = __float_as_uint(p0), u1 = __float_as_uint(p1);
            uint32_t u2 = __float_as_uint(p2), u3 = __float_as_uint(p3);
            float l0 = p0 - __uint_as_float(u0 & 0xFFFF0000u);
            float l1 = p1 - __uint_as_float(u1 & 0xFFFF0000u);
            float l2 = p2 - __uint_as_float(u2 & 0xFFFF0000u);
            float l3 = p3 - __uint_as_float(u3 & 0xFFFF0000u);
            int m = nb >> 1, sl = (nb & 1) * 2;
            Ph[m][sl]     = __byte_perm(u0, u1, 0x7632);
            Ph[m][sl + 1] = __byte_perm(u2, u3, 0x7632);
            uint32_t a, c;
            asm("cvt.rn.bf16x2.f32 %0, %1, %2;" : "=r"(a) : "f"(l1), "f"(l0));
            asm("cvt.rn.bf16x2.f32 %0, %1, %2;" : "=r"(c) : "f"(l3), "f"(l2));
            Pl[m][sl] = a; Pl[m][sl + 1] = c;
        }

        CP_WAIT(1);        // V[jt] landed (K[jt+1] may still be in flight)
        __syncthreads();

        // ---- D += P·V^T, 3-term split ----
#pragma unroll
        for (int m = 0; m < 4; m++) {
#pragma unroll
            for (int cb2 = 0; cb2 < 16; cb2++) {
                uint32_t vh[4], vl[4];
                uint32_t va = aV + (uint32_t)cb2 * (16 * RV) + m * 32;
                ldsm4(vh, va);
                ldsm4(vl, va + (SVL - SVH));
                mma_bf16(D[2 * cb2],     Ph[m], vh[0], vh[1]);
                mma_bf16(D[2 * cb2 + 1], Ph[m], vh[2], vh[3]);
                mma_bf16(D[2 * cb2],     Ph[m], vl[0], vl[1]);
                mma_bf16(D[2 * cb2 + 1], Ph[m], vl[2], vl[3]);
                mma_bf16(D[2 * cb2],     Pl[m], vh[0], vh[1]);
                mma_bf16(D[2 * cb2 + 1], Pl[m], vh[2], vh[3]);
            }
        }
        __syncthreads();   // V buffer free for next tile's issue
    }

    // ---- epilogue: reduce L over quad, normalize, fused writes ----
    L0 += __shfl_xor_sync(0xffffffffu, L0, 1);
    L0 += __shfl_xor_sync(0xffffffffu, L0, 2);
    L1 += __shfl_xor_sync(0xffffffffu, L1, 1);
    L1 += __shfl_xor_sync(0xffffffffu, L1, 2);
    const float inv0 = 1.0f / L0, inv1 = 1.0f / L1;
    const int ig0 = i0 + wid * 16 + g, ig8 = ig0 + 8;
    float* attn = out + (size_t)BATCH * CV * NPIX;
#pragma unroll
    for (int nb = 0; nb < 32; nb++) {
        int c = 8 * nb + 2 * t;
        size_t g0 = ((size_t)b * CV + c) * NPIX;
        float v00 = D[nb][0] * inv0, v01 = D[nb][1] * inv0;
        float v10 = D[nb][2] * inv1, v11 = D[nb][3] * inv1;
        out[g0 + ig0] = v00 * motion[g0 + ig0];               attn[g0 + ig0] = v00;
        out[g0 + NPIX + ig0] = v01 * motion[g0 + NPIX + ig0]; attn[g0 + NPIX + ig0] = v01;
        out[g0 + ig8] = v10 * motion[g0 + ig8];               attn[g0 + ig8] = v10;
        out[g0 + NPIX + ig8] = v11 * motion[g0 + NPIX + ig8]; attn[g0 + NPIX + ig8] = v11;
    }
}

// ============================================================================
extern "C" void kernel_launch(void* const* d_in, const int* in_sizes, int n_in,
                              void* d_out, int out_size)
{
    const float* a1  = (const float*)d_in[0];
    const float* a2  = (const float*)d_in[1];
    const float* mot = (const float*)d_in[2];
    const float* Wq  = (const float*)d_in[3];
    const float* bq  = (const float*)d_in[4];
    const float* Wk  = (const float*)d_in[5];
    const float* bk  = (const float*)d_in[6];
    const float* Wv  = (const float*)d_in[7];
    const float* bv  = (const float*)d_in[8];
    float* out = (float*)d_out;

    __nv_bfloat16 *Qh, *Ql, *Kh, *Kl, *Vh, *Vl;
    cudaGetSymbolAddress((void**)&Qh, g_Qhi);  cudaGetSymbolAddress((void**)&Ql, g_Qlo);
    cudaGetSymbolAddress((void**)&Kh, g_Khi);  cudaGetSymbolAddress((void**)&Kl, g_Klo);
    cudaGetSymbolAddress((void**)&Vh, g_Vthi); cudaGetSymbolAddress((void**)&Vl, g_Vtlo);

    const float LOG2E = 1.4426950408889634f;

    proj_split<CQK, CQK, false><<<dim3(NPIX / 64, 2, BATCH), 256>>>(a2, Wq, bq, Qh, Ql, LOG2E);
    proj_split<CQK, CQK, false><<<dim3(NPIX / 64, 2, BATCH), 256>>>(a1, Wk, bk, Kh, Kl, 1.0f);
    proj_split<CV,  CV,  true ><<<dim3(NPIX / 64, 4, BATCH), 256>>>(mot, Wv, bv, Vh, Vl, 1.0f);

    cudaFuncSetAttribute(flash_hmma, cudaFuncAttributeMaxDynamicSharedMemorySize, SMTOT);
    flash_hmma<<<dim3(NPIX / 128, BATCH), 256, SMTOT>>>(Qh, Ql, Kh, Kl, Vh, Vl, mot, out);
}